// round 1
// baseline (speedup 1.0000x reference)
#include <cuda_runtime.h>
#include <cuda_bf16.h>

#ifndef HELM_PI
#define HELM_PI 3.14159265358979323846f
#endif

// out[i] = (a^2 - 2*pi^2) * sin(pi*x0) * sin(pi*x1)
// Each thread processes 4 rows: two float4 loads (8 input floats), one float4 store.
__global__ void __launch_bounds__(256) helm_kernel(
    const float4* __restrict__ in4,   // interleaved [x0,x1] pairs, 2 rows per float4
    const float*  __restrict__ a,
    float4*       __restrict__ out4,  // 4 outputs per float4
    int n4)                            // number of output float4s = N/4
{
    int i = blockIdx.x * blockDim.x + threadIdx.x;
    if (i >= n4) return;

    const float pi = HELM_PI;
    float av = __ldg(a);
    float coef = fmaf(av, av, -2.0f * pi * pi);

    float4 v0 = in4[2 * i];      // rows 4i, 4i+1
    float4 v1 = in4[2 * i + 1];  // rows 4i+2, 4i+3

    float4 o;
    o.x = coef * __sinf(pi * v0.x) * __sinf(pi * v0.y);
    o.y = coef * __sinf(pi * v0.z) * __sinf(pi * v0.w);
    o.z = coef * __sinf(pi * v1.x) * __sinf(pi * v1.y);
    o.w = coef * __sinf(pi * v1.z) * __sinf(pi * v1.w);

    out4[i] = o;
}

extern "C" void kernel_launch(void* const* d_in, const int* in_sizes, int n_in,
                              void* d_out, int out_size)
{
    const float* in = (const float*)d_in[0];   // [N,2] float32
    const float* a  = (const float*)d_in[1];   // [1] float32

    int n = in_sizes[0] / 2;   // number of rows
    int n4 = n / 4;            // N = 2^24, divisible by 4

    const int threads = 256;
    int blocks = (n4 + threads - 1) / threads;

    helm_kernel<<<blocks, threads>>>(
        (const float4*)in, a, (float4*)d_out, n4);
}

// round 2
// speedup vs baseline: 1.0076x; 1.0076x over previous
#include <cuda_runtime.h>
#include <cuda_bf16.h>

#ifndef HELM_PI
#define HELM_PI 3.14159265358979323846f
#endif

// out[i] = (a^2 - 2*pi^2) * sin(pi*x0) * sin(pi*x1)
// Each thread processes 4 rows: two float4 loads (8 input floats), one float4 store.
__global__ void __launch_bounds__(256) helm_kernel(
    const float4* __restrict__ in4,   // interleaved [x0,x1] pairs, 2 rows per float4
    const float*  __restrict__ a,
    float4*       __restrict__ out4,  // 4 outputs per float4
    int n4)                            // number of output float4s = N/4
{
    int i = blockIdx.x * blockDim.x + threadIdx.x;
    if (i >= n4) return;

    const float pi = HELM_PI;
    float av = __ldg(a);
    float coef = fmaf(av, av, -2.0f * pi * pi);

    float4 v0 = in4[2 * i];      // rows 4i, 4i+1
    float4 v1 = in4[2 * i + 1];  // rows 4i+2, 4i+3

    float4 o;
    o.x = coef * __sinf(pi * v0.x) * __sinf(pi * v0.y);
    o.y = coef * __sinf(pi * v0.z) * __sinf(pi * v0.w);
    o.z = coef * __sinf(pi * v1.x) * __sinf(pi * v1.y);
    o.w = coef * __sinf(pi * v1.z) * __sinf(pi * v1.w);

    out4[i] = o;
}

extern "C" void kernel_launch(void* const* d_in, const int* in_sizes, int n_in,
                              void* d_out, int out_size)
{
    const float* in = (const float*)d_in[0];   // [N,2] float32
    const float* a  = (const float*)d_in[1];   // [1] float32

    int n = in_sizes[0] / 2;   // number of rows
    int n4 = n / 4;            // N = 2^24, divisible by 4

    const int threads = 256;
    int blocks = (n4 + threads - 1) / threads;

    helm_kernel<<<blocks, threads>>>(
        (const float4*)in, a, (float4*)d_out, n4);
}